// round 6
// baseline (speedup 1.0000x reference)
#include <cuda_runtime.h>
#include <cstdint>

// Problem constants (from reference_code)
constexpr int F     = 8;
constexpr int B     = 4096;
constexpr int L     = 20;
constexpr int BL    = B * L;        // 81920
constexpr int VOCAB = 1000000;
constexpr int DIM   = 128;          // 128 floats = 32 float4 per row
constexpr int ROWS  = F * BL;       // 655360 output rows
constexpr int R     = 8;            // rows per warp
constexpr int WARPS = 8;            // warps per block
constexpr int RPB   = R * WARPS;    // 64 rows per chunk
constexpr int CHUNKS = ROWS / RPB;  // 10240
constexpr int GRID  = 1280;         // persistent grid: 10240 / 1280 = 8 iters exactly
constexpr int ITERS = CHUNKS / GRID; // 8

// perm for SPLIT_SIZES=(4,4), SPLIT_ORDER=(1,0): [4,5,6,7,0,1,2,3] == (f+4)&7

__global__ __launch_bounds__(WARPS * 32)
void emb_gather_kernel(const int* __restrict__ vals,
                       const float4* __restrict__ table,
                       float4* __restrict__ out)
{
    __shared__ unsigned s_slot[2][RPB];

    const int tid  = threadIdx.x;
    const int warp = tid >> 5;
    const int lane = tid & 31;
    const int wbase = warp * R;

    // Prologue: stage slots for chunk 0 of this block.
    if (tid < RPB) {
        const int row   = blockIdx.x * RPB + tid;
        const int f     = row / BL;
        const int pos   = row - f * BL;
        const int src_f = (f + 4) & 7;               // feature permutation
        s_slot[0][tid] = (unsigned)__ldg(&vals[src_f * BL + pos]) % (unsigned)VOCAB;
    }
    __syncthreads();

    #pragma unroll 1
    for (int it = 0; it < ITERS; it++) {
        const int buf   = it & 1;
        const int chunk = blockIdx.x + it * GRID;
        const int base  = chunk * RPB;

        // Read this chunk's slots, launch 8 independent 512B row gathers.
        unsigned slot[R];
        #pragma unroll
        for (int r = 0; r < R; r++)
            slot[r] = s_slot[buf][wbase + r];

        float4 v[R];
        #pragma unroll
        for (int r = 0; r < R; r++)
            v[r] = __ldg(&table[(size_t)slot[r] * (DIM / 4) + lane]);

        // Prefetch next chunk's ids while row loads are in flight.
        unsigned nslot = 0;
        const bool more = (it + 1 < ITERS);
        if (more && tid < RPB) {
            const int nrow  = (blockIdx.x + (it + 1) * GRID) * RPB + tid;
            const int f     = nrow / BL;
            const int pos   = nrow - f * BL;
            const int src_f = (f + 4) & 7;
            nslot = (unsigned)__ldg(&vals[src_f * BL + pos]) % (unsigned)VOCAB;
        }

        // Streaming stores (evict-first keeps L2 for table rows).
        const size_t obase = (size_t)(base + wbase) * (DIM / 4) + lane;
        #pragma unroll
        for (int r = 0; r < R; r++)
            __stcs(&out[obase + (size_t)r * (DIM / 4)], v[r]);

        if (more && tid < RPB)
            s_slot[buf ^ 1][tid] = nslot;
        __syncthreads();
    }
}

extern "C" void kernel_launch(void* const* d_in, const int* in_sizes, int n_in,
                              void* d_out, int out_size)
{
    const int*    vals  = (const int*)d_in[0];     // [F, B*L] int32
    const float4* table = (const float4*)d_in[1];  // [VOCAB, DIM] float32
    float4*       out   = (float4*)d_out;          // [F, B*L, DIM] float32

    emb_gather_kernel<<<GRID, WARPS * 32>>>(vals, table, out);
}

// round 13
// speedup vs baseline: 1.0108x; 1.0108x over previous
#include <cuda_runtime.h>
#include <cstdint>

// Problem constants (from reference_code)
constexpr int F     = 8;
constexpr int B     = 4096;
constexpr int L     = 20;
constexpr int BL    = B * L;        // 81920
constexpr int VOCAB = 1000000;
constexpr int DIM   = 128;          // 512 bytes per row
constexpr int ROW_BYTES = DIM * 4;  // 512
constexpr int ROWS  = F * BL;       // 655360 output rows
constexpr int R     = 8;            // rows per warp (R | BL)

// perm for SPLIT_SIZES=(4,4), SPLIT_ORDER=(1,0): [4,5,6,7,0,1,2,3] == (f+4)&7

// 256-bit table load, L2 evict-last (sm_103a requires .v4.b64 for evict_last)
__device__ __forceinline__ void ldg_el_256(const char* p, uint64_t v[4])
{
    asm volatile("ld.global.nc.L2::evict_last.v4.b64 {%0,%1,%2,%3}, [%4];"
                 : "=l"(v[0]), "=l"(v[1]), "=l"(v[2]), "=l"(v[3]) : "l"(p));
}

// 256-bit streaming store (evict-first)
__device__ __forceinline__ void stg_cs_256(char* p, const uint64_t v[4])
{
    asm volatile("st.global.cs.v4.b64 [%0], {%1,%2,%3,%4};"
                 :: "l"(p), "l"(v[0]), "l"(v[1]), "l"(v[2]), "l"(v[3])
                 : "memory");
}

__global__ __launch_bounds__(256)
void emb_gather_kernel(const int* __restrict__ vals,
                       const char* __restrict__ table,
                       char* __restrict__ out)
{
    const int warp = (blockIdx.x * 256 + threadIdx.x) >> 5;
    const int lane = threadIdx.x & 31;

    const int base = warp * R;                 // first output row of this warp
    if (base >= ROWS) return;

    const int f   = base / BL;                 // all R rows share one feature
    const int pos = base - f * BL;
    const int src_f = (f + 4) & 7;             // feature-block permutation

    // lanes 0..R-1 fetch R consecutive ids (single 32B sector)
    int id = 0;
    if (lane < R) id = __ldg(&vals[src_f * BL + pos + lane]);

    unsigned slot[R];
    #pragma unroll
    for (int r = 0; r < R; r++)
        slot[r] = (unsigned)__shfl_sync(0xFFFFFFFFu, id, r) % (unsigned)VOCAB;

    // 256-bit lanes: lanes 0-15 -> row 2i, lanes 16-31 -> row 2i+1.
    const int half   = lane >> 4;              // which of the 2 rows
    const int within = (lane & 15) * 32;       // byte offset inside the row

    // 4 wide loads cover 8 rows; all independent (MLP=4 x 2-row).
    uint64_t v[R / 2][4];
    #pragma unroll
    for (int i = 0; i < R / 2; i++) {
        const unsigned s = slot[2 * i + half];
        ldg_el_256(table + (size_t)s * ROW_BYTES + within, v[i]);
    }

    // Streaming 256-bit stores, mirrored addressing.
    #pragma unroll
    for (int i = 0; i < R / 2; i++) {
        const size_t row = (size_t)(base + 2 * i + half);
        stg_cs_256(out + row * ROW_BYTES + within, v[i]);
    }
}

extern "C" void kernel_launch(void* const* d_in, const int* in_sizes, int n_in,
                              void* d_out, int out_size)
{
    const int*  vals  = (const int*)d_in[0];   // [F, B*L] int32
    const char* table = (const char*)d_in[1];  // [VOCAB, DIM] float32
    char*       out   = (char*)d_out;          // [F, B*L, DIM] float32

    const int threads = 256;
    const int rows_per_block = (threads / 32) * R; // 64
    const int blocks = ROWS / rows_per_block;      // 10240
    emb_gather_kernel<<<blocks, threads>>>(vals, table, out);
}

// round 14
// speedup vs baseline: 1.0121x; 1.0013x over previous
#include <cuda_runtime.h>
#include <cstdint>

// Problem constants (from reference_code)
constexpr int F     = 8;
constexpr int B     = 4096;
constexpr int L     = 20;
constexpr int BL    = B * L;        // 81920
constexpr int VOCAB = 1000000;
constexpr int DIM   = 128;          // 512 bytes per row
constexpr int ROW_BYTES = DIM * 4;  // 512
constexpr int ROWS  = F * BL;       // 655360 output rows
constexpr int R     = 4;            // rows per warp (fastest measured shape)

// perm for SPLIT_SIZES=(4,4), SPLIT_ORDER=(1,0): [4,5,6,7,0,1,2,3] == (f+4)&7

// 256-bit table load, L2 evict-last (sm_103a: evict_last requires .v4.b64)
__device__ __forceinline__ void ldg_el_256(const char* p, uint64_t v[4])
{
    asm volatile("ld.global.nc.L2::evict_last.v4.b64 {%0,%1,%2,%3}, [%4];"
                 : "=l"(v[0]), "=l"(v[1]), "=l"(v[2]), "=l"(v[3]) : "l"(p));
}

// 256-bit streaming store (evict-first)
__device__ __forceinline__ void stg_cs_256(char* p, const uint64_t v[4])
{
    asm volatile("st.global.cs.v4.b64 [%0], {%1,%2,%3,%4};"
                 :: "l"(p), "l"(v[0]), "l"(v[1]), "l"(v[2]), "l"(v[3])
                 : "memory");
}

__global__ __launch_bounds__(256)
void emb_gather_kernel(const int* __restrict__ vals,
                       const char* __restrict__ table,
                       char* __restrict__ out)
{
    const int warp = (blockIdx.x * 256 + threadIdx.x) >> 5;
    const int lane = threadIdx.x & 31;

    const int base = warp * R;                 // first output row of this warp
    if (base >= ROWS) return;

    const int f   = base / BL;                 // all R rows share one feature
    const int pos = base - f * BL;
    const int src_f = (f + 4) & 7;             // feature-block permutation

    // lanes 0..R-1 fetch R consecutive ids (single 16B sector)
    int id = 0;
    if (lane < R) id = __ldg(&vals[src_f * BL + pos + lane]);

    unsigned slot[R];
    #pragma unroll
    for (int r = 0; r < R; r++)
        slot[r] = (unsigned)__shfl_sync(0xFFFFFFFFu, id, r) % (unsigned)VOCAB;

    // 256-bit lanes: lanes 0-15 -> row 2i, lanes 16-31 -> row 2i+1.
    const int half   = lane >> 4;              // which of the pair's 2 rows
    const int within = (lane & 15) * 32;       // byte offset inside the row

    // 2 wide loads cover 4 rows; independent (2 x 2-row MLP).
    uint64_t v[R / 2][4];
    #pragma unroll
    for (int i = 0; i < R / 2; i++) {
        const unsigned s = slot[2 * i + half];
        ldg_el_256(table + (size_t)s * ROW_BYTES + within, v[i]);
    }

    // Streaming 256-bit stores, mirrored addressing.
    #pragma unroll
    for (int i = 0; i < R / 2; i++) {
        const size_t row = (size_t)(base + 2 * i + half);
        stg_cs_256(out + row * ROW_BYTES + within, v[i]);
    }
}

extern "C" void kernel_launch(void* const* d_in, const int* in_sizes, int n_in,
                              void* d_out, int out_size)
{
    const int*  vals  = (const int*)d_in[0];   // [F, B*L] int32
    const char* table = (const char*)d_in[1];  // [VOCAB, DIM] float32
    char*       out   = (char*)d_out;          // [F, B*L, DIM] float32

    const int threads = 256;
    const int rows_per_block = (threads / 32) * R; // 32
    const int blocks = ROWS / rows_per_block;      // 20480
    emb_gather_kernel<<<blocks, threads>>>(vals, table, out);
}